// round 13
// baseline (speedup 1.0000x reference)
#include <cuda_runtime.h>
#include <cuda_bf16.h>
#include <math.h>
#include <stdint.h>

// Problem constants: B=8, S=4096, H=8, D=128, K=32
#define H_   8
#define D_   128
#define K_   32
#define NTOK 32768
#define HD   1024

typedef unsigned long long u64;

__device__ __forceinline__ uint32_t pack_bf16(float hi, float lo) {
    uint32_t r;
    asm("cvt.rn.bf16x2.f32 %0, %1, %2;" : "=r"(r) : "f"(hi), "f"(lo));
    return r;
}
static __device__ __forceinline__ uint32_t smem_u32(const void* p) {
    uint32_t a;
    asm("{ .reg .u64 t; cvta.to.shared.u64 t, %1; cvt.u32.u64 %0, t; }" : "=r"(a) : "l"(p));
    return a;
}
__device__ __forceinline__ void ldsm4(uint32_t& a0, uint32_t& a1, uint32_t& a2, uint32_t& a3,
                                      uint32_t addr) {
    asm volatile("ldmatrix.sync.aligned.m8n8.x4.shared.b16 {%0,%1,%2,%3}, [%4];"
                 : "=r"(a0), "=r"(a1), "=r"(a2), "=r"(a3) : "r"(addr));
}
__device__ __forceinline__ void ldsm4t(uint32_t& a0, uint32_t& a1, uint32_t& a2, uint32_t& a3,
                                       uint32_t addr) {
    asm volatile("ldmatrix.sync.aligned.m8n8.x4.trans.shared.b16 {%0,%1,%2,%3}, [%4];"
                 : "=r"(a0), "=r"(a1), "=r"(a2), "=r"(a3) : "r"(addr));
}
__device__ __forceinline__ void mma16816(float* d, uint32_t a0, uint32_t a1, uint32_t a2,
                                         uint32_t a3, uint32_t b0, uint32_t b1) {
    asm volatile("mma.sync.aligned.m16n8k16.row.col.f32.bf16.bf16.f32 "
                 "{%0,%1,%2,%3}, {%4,%5,%6,%7}, {%8,%9}, {%0,%1,%2,%3};"
                 : "+f"(d[0]), "+f"(d[1]), "+f"(d[2]), "+f"(d[3])
                 : "r"(a0), "r"(a1), "r"(a2), "r"(a3), "r"(b0), "r"(b1));
}
// bf16x2 word -> packed f32x2 {lo<<16, hi&mask} — BOTH exact
__device__ __forceinline__ u64 pk_exact(uint32_t w) {
    u64 d;
    asm("{ .reg .b32 lo, hi; shl.b32 lo, %1, 16; and.b32 hi, %1, 0xffff0000;"
        " mov.b64 %0, {lo, hi}; }" : "=l"(d) : "r"(w));
    return d;
}
__device__ __forceinline__ u64 add2(u64 a, u64 b) {
    u64 d;
    asm("add.rn.f32x2 %0, %1, %2;" : "=l"(d) : "l"(a), "l"(b));
    return d;
}
__device__ __forceinline__ u64 ffma2(u64 a, u64 b, u64 c) {
    u64 d;
    asm("fma.rn.f32x2 %0, %1, %2, %3;" : "=l"(d) : "l"(a), "l"(b), "l"(c));
    return d;
}
__device__ __forceinline__ float2 unpack2(u64 v) {
    float2 r;
    asm("mov.b64 {%0, %1}, %2;" : "=f"(r.x), "=f"(r.y) : "l"(v));
    return r;
}

// Scratch
__device__ __nv_bfloat16 g_a[(size_t)H_ * 256 * 8 * 512];   // 16 MB GELU activations
__device__ float g_part[H_ * 256 * 1088];                   // per-(head,block) M + s
__device__ float g_A[HD];
__device__ float g_C2[HD];
__device__ __align__(16) __nv_bfloat16 g_wdg[H_ * 32 * 136];  // [h][k][d], stride 136
__device__ __align__(16) __nv_bfloat16 g_wut[H_ * 128 * 40];  // [h][d][k], stride 40
__device__ float g_P[H_ * K_], g_Q[H_ * K_];

// K1 dynamic SMEM (bytes)
#define SO_WDG  0          // 8704
#define SO_P    8704       // 128
#define SO_Q    8832       // 128
#define SO_WARP 8960       // 8 warps * 5632
// per-warp slab: [0,4352) x tile (stride 272) -> reused: [0,1280) a_stage (stride 80),
//                [1280,5504) M (32x33 fp32), [5504,5632) s (32 fp32)
#define SLAB    5632
#define SMEM_BYTES (8960 + 8 * SLAB)   // 54016

// ---------------------------------------------------------------------------
// K0: weight preprocessing. grid = 32 (4 per head), block = 128.
// ---------------------------------------------------------------------------
__global__ void __launch_bounds__(128) adapter_k0(
    const float* __restrict__ lng, const float* __restrict__ lnb,
    const float* __restrict__ wd,  const float* __restrict__ bd,
    const float* __restrict__ wu)
{
    const int h = blockIdx.x >> 2, p = blockIdx.x & 3;
    const int tid = threadIdx.x;
    for (int i = p * 1024 + tid; i < (p + 1) * 1024; i += 128) {
        int d = i >> 5, k = i & 31;                      // wd[h][d][k]
        g_wdg[h * 4352 + k * 136 + d] =
            __float2bfloat16(lng[h * 128 + d] * wd[h * 4096 + i]);
    }
    for (int i = p * 1024 + tid; i < (p + 1) * 1024; i += 128) {
        int k = i >> 7, d = i & 127;                     // wu[h][k][d]
        g_wut[h * 5120 + d * 40 + k] = __float2bfloat16(wu[h * 4096 + i]);
    }
    if (p == 0 && tid < K_) {
        float pp = 0.f, q = bd[h * K_ + tid];
        #pragma unroll 4
        for (int d = 0; d < D_; d++) {
            float v = lng[h * 128 + d] * wd[h * 4096 + d * 32 + tid];
            pp += __bfloat162float(__float2bfloat16(v));  // bf16-rounded, as GEMM sees
            q += lnb[h * 128 + d] * wd[h * 4096 + d * 32 + tid];
        }
        g_P[h * K_ + tid] = pp;
        g_Q[h * K_ + tid] = q;
    }
}

// ---------------------------------------------------------------------------
// K1: LN+GEMM1+GELU -> store a; Gram M = a^T a + s via HMMA.
// grid = (256, H), block = 256 (8 warps). Warp: 16 tokens.
// ---------------------------------------------------------------------------
__global__ void __launch_bounds__(256, 3) adapter_k1(const float* __restrict__ x)
{
    extern __shared__ __align__(16) char smc[];
    __nv_bfloat16* wdg_s = (__nv_bfloat16*)(smc + SO_WDG);
    float* P_s  = (float*)(smc + SO_P);
    float* Q_s  = (float*)(smc + SO_Q);

    const int tid = threadIdx.x;
    const int h = blockIdx.y;
    const int blk = blockIdx.x;

    {   // weights -> SMEM
        const uint4* s1 = (const uint4*)(g_wdg + h * 4352);
        uint4* d1 = (uint4*)wdg_s;
        for (int i = tid; i < 544; i += 256) d1[i] = s1[i];
        if (tid < 32) { P_s[tid] = g_P[h * K_ + tid]; Q_s[tid] = g_Q[h * K_ + tid]; }
    }
    __syncthreads();

    const int w = tid >> 5, l = tid & 31;
    const int gr = l >> 2, gc = l & 3;
    char* slab = smc + SO_WARP + w * SLAB;
    const size_t tok0 = (size_t)blk * 128 + (size_t)w * 16;
    const float* xb = x + tok0 * HD + h * 128;

    // ---- load x -> bf16 tile (stride 272) ----
    #pragma unroll
    for (int r = 0; r < 16; r++) {
        float4 v = *(const float4*)(xb + (size_t)r * HD + l * 4);
        *(uint2*)(slab + r * 272 + l * 8) =
            make_uint2(pack_bf16(v.y, v.x), pack_bf16(v.w, v.z));
    }
    __syncwarp();

    // ---- LN stats (exact f32x2 on rounded values) ----
    float mu0, rs0, mu1, rs1;
    {
        const uint4* rp = (const uint4*)(slab + (l & 15) * 272 + (l >> 4) * 128);
        u64 s2 = 0ull, q2 = 0ull;
        #pragma unroll
        for (int i = 0; i < 8; i++) {
            uint4 v = rp[i];
            u64 p0 = pk_exact(v.x), p1 = pk_exact(v.y);
            u64 p2 = pk_exact(v.z), p3 = pk_exact(v.w);
            s2 = add2(s2, p0); q2 = ffma2(p0, p0, q2);
            s2 = add2(s2, p1); q2 = ffma2(p1, p1, q2);
            s2 = add2(s2, p2); q2 = ffma2(p2, p2, q2);
            s2 = add2(s2, p3); q2 = ffma2(p3, p3, q2);
        }
        float2 sf = unpack2(s2), qf = unpack2(q2);
        float s = sf.x + sf.y, q = qf.x + qf.y;
        s += __shfl_xor_sync(0xffffffffu, s, 16);
        q += __shfl_xor_sync(0xffffffffu, q, 16);
        const float mu = s * (1.f / 128.f);
        const float rs = rsqrtf(fmaxf(q * (1.f / 128.f) - mu * mu, 0.f) + 1e-5f);
        mu0 = __shfl_sync(0xffffffffu, mu, gr);
        rs0 = __shfl_sync(0xffffffffu, rs, gr);
        mu1 = __shfl_sync(0xffffffffu, mu, gr + 8);
        rs1 = __shfl_sync(0xffffffffu, rs, gr + 8);
    }

    // ---- GEMM1 ----
    float D1[4][4] = {};
    {
        const uint32_t xab = smem_u32(slab);
        const int mid = l >> 3;
        const uint32_t abase = xab + ((l & 7) + ((mid & 1) << 3)) * 272 + ((mid >> 1) << 4);
        const uint32_t* wdgw = (const uint32_t*)wdg_s;
        #pragma unroll
        for (int kt = 0; kt < 8; kt++) {
            uint32_t a0, a1, a2, a3;
            ldsm4(a0, a1, a2, a3, abase + kt * 32);
            #pragma unroll
            for (int j = 0; j < 4; j++) {
                const uint32_t* bp = wdgw + (8 * j + gr) * 68 + kt * 8 + gc;
                mma16816(D1[j], a0, a1, a2, a3, bp[0], bp[4]);
            }
        }
    }

    // ---- epilogue 1: LN finalize + exact GELU -> A2 frags ----
    uint32_t A2[2][4];
    #pragma unroll
    for (int j = 0; j < 4; j++) {
        const int k0 = 8 * j + 2 * gc;
        const float2 Pp = *(const float2*)(P_s + k0);
        const float2 Qp = *(const float2*)(Q_s + k0);
        float v00 = rs0 * (D1[j][0] - mu0 * Pp.x) + Qp.x;
        float v01 = rs0 * (D1[j][1] - mu0 * Pp.y) + Qp.y;
        float v10 = rs1 * (D1[j][2] - mu1 * Pp.x) + Qp.x;
        float v11 = rs1 * (D1[j][3] - mu1 * Pp.y) + Qp.y;
        v00 = 0.5f * v00 * (1.f + erff(v00 * 0.7071067811865476f));
        v01 = 0.5f * v01 * (1.f + erff(v01 * 0.7071067811865476f));
        v10 = 0.5f * v10 * (1.f + erff(v10 * 0.7071067811865476f));
        v11 = 0.5f * v11 * (1.f + erff(v11 * 0.7071067811865476f));
        A2[j >> 1][(j & 1) << 1]       = pack_bf16(v01, v00);
        A2[j >> 1][((j & 1) << 1) | 1] = pack_bf16(v11, v10);
    }
    __syncwarp();   // x tile fully consumed

    // ---- stage a row-major (stride 40 bf16 = 20 words): conflict-free STS ----
    {
        uint32_t* asw = (uint32_t*)slab;
        #pragma unroll
        for (int j = 0; j < 4; j++) {
            asw[gr * 20 + 4 * j + gc]       = A2[j >> 1][(j & 1) << 1];
            asw[(gr + 8) * 20 + 4 * j + gc] = A2[j >> 1][((j & 1) << 1) | 1];
        }
    }
    __syncwarp();

    // ---- coalesced a -> gmem (compact 16x32 bf16 = 1 KB per warp) ----
    {
        const int row = l & 15, hf = l >> 4;
        uint4 v0 = *(const uint4*)(slab + row * 80 + hf * 32);
        uint4 v1 = *(const uint4*)(slab + row * 80 + hf * 32 + 16);
        __nv_bfloat16* gp = g_a + (((size_t)h * 256 + blk) * 8 + w) * 512
                            + row * 32 + hf * 16;
        *(uint4*)(gp)     = v0;
        *(uint4*)(gp + 8) = v1;
    }

    // ---- Gram: M = a^T a (8 mma), s via shfl ----
    float DM[2][4][4] = {};
    uint32_t GA[2][4], GB[2][4];
    {
        const uint32_t ab = smem_u32(slab);
        #pragma unroll
        for (int mt = 0; mt < 2; mt++) {
            uint32_t addr = ab + ((l & 7) + 8 * ((l >> 4) & 1)) * 80
                          + ((l >> 3) & 1) * 16 + mt * 32;
            ldsm4t(GA[mt][0], GA[mt][1], GA[mt][2], GA[mt][3], addr);
        }
        #pragma unroll
        for (int pr = 0; pr < 2; pr++) {
            uint32_t addr = ab + ((l & 7) + 8 * ((l >> 3) & 1)) * 80
                          + ((l >> 4) & 1) * 16 + pr * 32;
            ldsm4t(GB[pr][0], GB[pr][1], GB[pr][2], GB[pr][3], addr);
        }
        #pragma unroll
        for (int mt = 0; mt < 2; mt++)
            #pragma unroll
            for (int nt = 0; nt < 4; nt++)
                mma16816(DM[mt][nt], GA[mt][0], GA[mt][1], GA[mt][2], GA[mt][3],
                         GB[nt >> 1][(nt & 1) << 1], GB[nt >> 1][((nt & 1) << 1) | 1]);
    }

    // ---- write M (32x33 pad) + s into slab ----
    {
        float* Mw = (float*)(slab + 1280);
        float* sW = (float*)(slab + 5504);
        #pragma unroll
        for (int mt = 0; mt < 2; mt++) {
            // s: sum over tokens of a^T rows
            float2 f0 = unpack2(add2(pk_exact(GA[mt][0]), pk_exact(GA[mt][2])));
            float2 f1 = unpack2(add2(pk_exact(GA[mt][1]), pk_exact(GA[mt][3])));
            float p1 = f0.x + f0.y, p2 = f1.x + f1.y;
            p1 += __shfl_xor_sync(0xffffffffu, p1, 1);
            p1 += __shfl_xor_sync(0xffffffffu, p1, 2);
            p2 += __shfl_xor_sync(0xffffffffu, p2, 1);
            p2 += __shfl_xor_sync(0xffffffffu, p2, 2);
            if (gc == 0) {
                sW[16 * mt + gr]     = p1;
                sW[16 * mt + 8 + gr] = p2;
            }
            #pragma unroll
            for (int nt = 0; nt < 4; nt++) {
                const int r0 = 16 * mt + gr, c0 = 8 * nt + 2 * gc;
                Mw[r0 * 33 + c0]           = DM[mt][nt][0];
                Mw[r0 * 33 + c0 + 1]       = DM[mt][nt][1];
                Mw[(r0 + 8) * 33 + c0]     = DM[mt][nt][2];
                Mw[(r0 + 8) * 33 + c0 + 1] = DM[mt][nt][3];
            }
        }
    }
    __syncthreads();

    // ---- deterministic block reduce over 8 warps -> g_part ----
    const float* sbase = (const float*)(smc + SO_WARP);
    float* gp = g_part + ((size_t)h * 256 + blk) * 1088;
    for (int i = tid; i < 1088; i += 256) {
        const int word = (i < 1056) ? (320 + i) : (1376 + (i - 1056));
        float a = 0.f;
        #pragma unroll
        for (int w2 = 0; w2 < 8; w2++) a += sbase[w2 * (SLAB / 4) + word];
        gp[i] = a;
    }
}

// ---------------------------------------------------------------------------
// K2: reduce M,s; per-feature algebraic BN -> A, C2. grid = H, block = 1024.
// ---------------------------------------------------------------------------
__global__ void __launch_bounds__(1024) adapter_k2(const float* __restrict__ bu,
                                                   const float* __restrict__ bng,
                                                   const float* __restrict__ bnb)
{
    __shared__ float buf[1088];
    const int tid = threadIdx.x;
    const int h = blockIdx.x;
    for (int i = tid; i < 1088; i += 1024) {
        float acc = 0.f;
        const float* gp = g_part + (size_t)h * 256 * 1088 + i;
        #pragma unroll 8
        for (int b = 0; b < 256; b++) acc += gp[(size_t)b * 1088];
        buf[i] = acc;
    }
    __syncthreads();
    if (tid < 128) {
        const int d = tid;
        float wv[32];
        #pragma unroll
        for (int k = 0; k < 32; k++)
            wv[k] = __bfloat162float(g_wut[h * 5120 + d * 40 + k]);
        float dot = 0.f;
        #pragma unroll
        for (int k = 0; k < 32; k++) dot += buf[1056 + k] * wv[k];
        float quad = 0.f;
        #pragma unroll 4
        for (int k = 0; k < 32; k++) {
            float inner = 0.f;
            #pragma unroll
            for (int k2 = 0; k2 < 32; k2++) inner += buf[k * 33 + k2] * wv[k2];
            quad += wv[k] * inner;
        }
        const float bud = bu[h * 128 + d];
        const float inv = 1.f / (float)NTOK;
        const float mean = dot * inv + bud;
        const float Esq  = (quad + 2.f * bud * dot) * inv + bud * bud;
        const float var  = fmaxf(Esq - mean * mean, 0.f);
        const float rsv  = rsqrtf(var + 1e-5f);
        const int f = h * 128 + d;
        const float A = 0.1f * bng[f] * rsv;
        g_A[f]  = A;
        g_C2[f] = A * (bud - mean) + 0.1f * bnb[f];
    }
}

// ---------------------------------------------------------------------------
// K3: out = (a @ Wu)*A + C2 + x. grid = (256, H), block = 256 (8 warps).
// ---------------------------------------------------------------------------
__global__ void __launch_bounds__(256, 3) adapter_k3(const float* __restrict__ x,
                                                     float* __restrict__ out)
{
    __shared__ __align__(16) __nv_bfloat16 wut_s[128 * 40];
    __shared__ float As[128], Cs[128];

    const int tid = threadIdx.x;
    const int h = blockIdx.y;
    const int blk = blockIdx.x;

    {
        const uint4* s2 = (const uint4*)(g_wut + h * 5120);
        uint4* d2 = (uint4*)wut_s;
        for (int i = tid; i < 640; i += 256) d2[i] = s2[i];
        if (tid < 128) { As[tid] = g_A[h * 128 + tid]; Cs[tid] = g_C2[h * 128 + tid]; }
    }
    __syncthreads();

    const int w = tid >> 5, l = tid & 31;
    const int gr = l >> 2, gc = l & 3;
    const size_t tok0 = (size_t)blk * 128 + (size_t)w * 16;
    const __nv_bfloat16* ga = g_a + (((size_t)h * 256 + blk) * 8 + w) * 512;

    // A-fragments of a (row=token, col=k) straight from gmem (sector-packed)
    uint32_t AF[2][4];
    #pragma unroll
    for (int kt = 0; kt < 2; kt++) {
        AF[kt][0] = *(const uint32_t*)(ga + gr * 32 + kt * 16 + 2 * gc);
        AF[kt][1] = *(const uint32_t*)(ga + (gr + 8) * 32 + kt * 16 + 2 * gc);
        AF[kt][2] = *(const uint32_t*)(ga + gr * 32 + kt * 16 + 8 + 2 * gc);
        AF[kt][3] = *(const uint32_t*)(ga + (gr + 8) * 32 + kt * 16 + 8 + 2 * gc);
    }

    const uint32_t* wutw = (const uint32_t*)wut_s;
    const float* xr0 = x + (tok0 + gr) * HD + h * 128;
    const float* xr1 = x + (tok0 + gr + 8) * HD + h * 128;
    float* or0 = out + (tok0 + gr) * HD + h * 128;
    float* or1 = out + (tok0 + gr + 8) * HD + h * 128;

    #pragma unroll
    for (int half = 0; half < 2; half++) {
        float D2[8][4] = {};
        #pragma unroll
        for (int j = 0; j < 8; j++) {
            const uint32_t* bp = wutw + (half * 64 + 8 * j + gr) * 20 + gc;
            mma16816(D2[j], AF[0][0], AF[0][1], AF[0][2], AF[0][3], bp[0], bp[4]);
            mma16816(D2[j], AF[1][0], AF[1][1], AF[1][2], AF[1][3], bp[8], bp[12]);
        }
        #pragma unroll
        for (int j = 0; j < 8; j++) {
            const int n0 = half * 64 + 8 * j + 2 * gc;
            const float2 Av = *(const float2*)(As + n0);
            const float2 Cv = *(const float2*)(Cs + n0);
            const float2 x0 = *(const float2*)(xr0 + n0);
            const float2 x1 = *(const float2*)(xr1 + n0);
            float2 o0, o1;
            o0.x = D2[j][0] * Av.x + Cv.x + x0.x;
            o0.y = D2[j][1] * Av.y + Cv.y + x0.y;
            o1.x = D2[j][2] * Av.x + Cv.x + x1.x;
            o1.y = D2[j][3] * Av.y + Cv.y + x1.y;
            *(float2*)(or0 + n0) = o0;
            *(float2*)(or1 + n0) = o1;
        }
    }
}

// ---------------------------------------------------------------------------
extern "C" void kernel_launch(void* const* d_in, const int* in_sizes, int n_in,
                              void* d_out, int out_size)
{
    const float* x   = (const float*)d_in[0];
    const float* lng = (const float*)d_in[1];
    const float* lnb = (const float*)d_in[2];
    const float* wd  = (const float*)d_in[3];
    const float* bd  = (const float*)d_in[4];
    const float* wu  = (const float*)d_in[5];
    const float* bu  = (const float*)d_in[6];
    const float* bng = (const float*)d_in[7];
    const float* bnb = (const float*)d_in[8];
    float* out = (float*)d_out;

    cudaFuncSetAttribute(adapter_k1, cudaFuncAttributeMaxDynamicSharedMemorySize, SMEM_BYTES);

    adapter_k0<<<32, 128>>>(lng, lnb, wd, bd, wu);
    adapter_k1<<<dim3(256, H_), 256, SMEM_BYTES>>>(x);
    adapter_k2<<<H_, 1024>>>(bu, bng, bnb);
    adapter_k3<<<dim3(256, H_), 256>>>(x, out);
}

// round 14
// speedup vs baseline: 1.2502x; 1.2502x over previous
#include <cuda_runtime.h>
#include <cuda_bf16.h>
#include <math.h>
#include <stdint.h>

// Problem constants: B=8, S=4096, H=8, D=128, K=32
#define H_   8
#define D_   128
#define K_   32
#define NTOK 32768
#define HD   1024

typedef unsigned long long u64;

__device__ __forceinline__ uint32_t pack_bf16(float hi, float lo) {
    uint32_t r;
    asm("cvt.rn.bf16x2.f32 %0, %1, %2;" : "=r"(r) : "f"(hi), "f"(lo));
    return r;
}
static __device__ __forceinline__ uint32_t smem_u32(const void* p) {
    uint32_t a;
    asm("{ .reg .u64 t; cvta.to.shared.u64 t, %1; cvt.u32.u64 %0, t; }" : "=r"(a) : "l"(p));
    return a;
}
__device__ __forceinline__ void ldsm4(uint32_t& a0, uint32_t& a1, uint32_t& a2, uint32_t& a3,
                                      uint32_t addr) {
    asm volatile("ldmatrix.sync.aligned.m8n8.x4.shared.b16 {%0,%1,%2,%3}, [%4];"
                 : "=r"(a0), "=r"(a1), "=r"(a2), "=r"(a3) : "r"(addr));
}
__device__ __forceinline__ void mma16816(float* d, uint32_t a0, uint32_t a1, uint32_t a2,
                                         uint32_t a3, uint32_t b0, uint32_t b1) {
    asm volatile("mma.sync.aligned.m16n8k16.row.col.f32.bf16.bf16.f32 "
                 "{%0,%1,%2,%3}, {%4,%5,%6,%7}, {%8,%9}, {%0,%1,%2,%3};"
                 : "+f"(d[0]), "+f"(d[1]), "+f"(d[2]), "+f"(d[3])
                 : "r"(a0), "r"(a1), "r"(a2), "r"(a3), "r"(b0), "r"(b1));
}
// bf16x2 word -> packed f32x2 {lo<<16, hi&mask} — BOTH exact
__device__ __forceinline__ u64 pk_exact(uint32_t w) {
    u64 d;
    asm("{ .reg .b32 lo, hi; shl.b32 lo, %1, 16; and.b32 hi, %1, 0xffff0000;"
        " mov.b64 %0, {lo, hi}; }" : "=l"(d) : "r"(w));
    return d;
}
__device__ __forceinline__ u64 add2(u64 a, u64 b) {
    u64 d;
    asm("add.rn.f32x2 %0, %1, %2;" : "=l"(d) : "l"(a), "l"(b));
    return d;
}
__device__ __forceinline__ u64 ffma2(u64 a, u64 b, u64 c) {
    u64 d;
    asm("fma.rn.f32x2 %0, %1, %2, %3;" : "=l"(d) : "l"(a), "l"(b), "l"(c));
    return d;
}
__device__ __forceinline__ float2 unpack2(u64 v) {
    float2 r;
    asm("mov.b64 {%0, %1}, %2;" : "=f"(r.x), "=f"(r.y) : "l"(v));
    return r;
}

// Scratch
__device__ __nv_bfloat16 g_h[(size_t)NTOK * HD];        // 64 MB h (bf16)
__device__ float g_part[H_ * 256 * 256];                // per-(head,block) BN partials
__device__ float g_mid[H_ * 8 * 256];                   // stage-1 reduction
__device__ float g_A[HD];
__device__ float g_C[HD];
__device__ __align__(16) __nv_bfloat16 g_wdg[H_ * 32 * 136];  // [h][k][d], stride 136
__device__ __align__(16) __nv_bfloat16 g_wut[H_ * 128 * 40];  // [h][d][k], stride 40
__device__ float g_P[H_ * K_], g_Q[H_ * K_];

// Dynamic SMEM layout for K1 (bytes)
#define SO_WDG 0          // 8704
#define SO_WUT 8704       // 10240
#define SO_BUB 18944      // 512
#define SO_P   19456      // 128
#define SO_Q   19584      // 128
#define SO_XA  19712      // 8 warps * 16*136*2 = 34816
#define SO_ST  54528      // 8 warps * 256 floats = 8192 (BN partials)
#define SMEM_BYTES 62720

// ---------------------------------------------------------------------------
// K0: weight preprocessing. grid = 32 (4 per head), block = 128.
// ---------------------------------------------------------------------------
__global__ void __launch_bounds__(128) adapter_k0(
    const float* __restrict__ lng, const float* __restrict__ lnb,
    const float* __restrict__ wd,  const float* __restrict__ bd,
    const float* __restrict__ wu)
{
    const int h = blockIdx.x >> 2, p = blockIdx.x & 3;
    const int tid = threadIdx.x;
    for (int i = p * 1024 + tid; i < (p + 1) * 1024; i += 128) {
        int d = i >> 5, k = i & 31;                      // wd[h][d][k]
        g_wdg[h * 4352 + k * 136 + d] =
            __float2bfloat16(lng[h * 128 + d] * wd[h * 4096 + i]);
    }
    for (int i = p * 1024 + tid; i < (p + 1) * 1024; i += 128) {
        int k = i >> 7, d = i & 127;                     // wu[h][k][d]
        g_wut[h * 5120 + d * 40 + k] = __float2bfloat16(wu[h * 4096 + i]);
    }
    if (p == 0 && tid < K_) {
        float pp = 0.f, q = bd[h * K_ + tid];
        #pragma unroll 4
        for (int d = 0; d < D_; d++) {
            float v = lng[h * 128 + d] * wd[h * 4096 + d * 32 + tid];
            pp += __bfloat162float(__float2bfloat16(v));  // bf16-rounded, as GEMM sees
            q += lnb[h * 128 + d] * wd[h * 4096 + d * 32 + tid];
        }
        g_P[h * K_ + tid] = pp;
        g_Q[h * K_ + tid] = q;
    }
}

// ---------------------------------------------------------------------------
// K1: HMMA pipeline + fused BN partials. grid = (256, H), block = 256 (8 warps).
//   down[k] = rs*(S[k] - mu*P[k]) + Q[k];  S from mma on raw bf16 x.
// ---------------------------------------------------------------------------
__global__ void __launch_bounds__(256, 3) adapter_k1(
    const float* __restrict__ x, const float* __restrict__ bu)
{
    extern __shared__ __align__(16) char smc[];
    __nv_bfloat16* wdg_s = (__nv_bfloat16*)(smc + SO_WDG);
    __nv_bfloat16* wut_s = (__nv_bfloat16*)(smc + SO_WUT);
    float* bu_s = (float*)(smc + SO_BUB);
    float* P_s  = (float*)(smc + SO_P);
    float* Q_s  = (float*)(smc + SO_Q);
    float* st_s = (float*)(smc + SO_ST);

    const int tid = threadIdx.x;
    const int h = blockIdx.y;

    {   // weights -> SMEM (shared by 8 warps)
        const uint4* s1 = (const uint4*)(g_wdg + h * 4352);
        uint4* d1 = (uint4*)wdg_s;
        for (int i = tid; i < 544; i += 256) d1[i] = s1[i];
        const uint4* s2 = (const uint4*)(g_wut + h * 5120);
        uint4* d2 = (uint4*)wut_s;
        for (int i = tid; i < 640; i += 256) d2[i] = s2[i];
        if (tid < 32) { P_s[tid] = g_P[h * K_ + tid]; Q_s[tid] = g_Q[h * K_ + tid]; }
        if (tid < 128) bu_s[tid] = bu[h * 128 + tid];
    }
    __syncthreads();

    const int w = tid >> 5, l = tid & 31;
    const int gr = l >> 2, gc = l & 3;
    __nv_bfloat16* xa = (__nv_bfloat16*)(smc + SO_XA) + w * (16 * 136);
    uint32_t* xaw = (uint32_t*)xa;
    const size_t tok0 = (size_t)blockIdx.x * 128 + (size_t)w * 16;
    const float* xb = x + tok0 * HD + h * 128;

    // ---- load x -> bf16 tile (no reductions in the load loop) ----
    #pragma unroll
    for (int r = 0; r < 16; r++) {
        float4 v = *(const float4*)(xb + (size_t)r * HD + l * 4);
        *(uint2*)((char*)xa + r * 272 + l * 8) =
            make_uint2(pack_bf16(v.y, v.x), pack_bf16(v.w, v.z));
    }
    __syncwarp();

    // ---- LN stats from SMEM: lane = (row l&15, half l>>4), exact f32x2 ----
    float mu0, rs0, mu1, rs1;
    {
        const uint4* rp = (const uint4*)((const char*)xa + (l & 15) * 272 + (l >> 4) * 128);
        u64 s2 = 0ull, q2 = 0ull;
        #pragma unroll
        for (int i = 0; i < 8; i++) {
            uint4 v = rp[i];
            u64 p0 = pk_exact(v.x), p1 = pk_exact(v.y);
            u64 p2 = pk_exact(v.z), p3 = pk_exact(v.w);
            s2 = add2(s2, p0); q2 = ffma2(p0, p0, q2);
            s2 = add2(s2, p1); q2 = ffma2(p1, p1, q2);
            s2 = add2(s2, p2); q2 = ffma2(p2, p2, q2);
            s2 = add2(s2, p3); q2 = ffma2(p3, p3, q2);
        }
        float2 sf = unpack2(s2), qf = unpack2(q2);
        float s = sf.x + sf.y, q = qf.x + qf.y;
        s += __shfl_xor_sync(0xffffffffu, s, 16);
        q += __shfl_xor_sync(0xffffffffu, q, 16);
        const float mu = s * (1.f / 128.f);
        const float rs = rsqrtf(fmaxf(q * (1.f / 128.f) - mu * mu, 0.f) + 1e-5f);
        mu0 = __shfl_sync(0xffffffffu, mu, gr);
        rs0 = __shfl_sync(0xffffffffu, rs, gr);
        mu1 = __shfl_sync(0xffffffffu, mu, gr + 8);
        rs1 = __shfl_sync(0xffffffffu, rs, gr + 8);
    }

    // ---- GEMM1: D1[16 tok x 32 k] = x_tile[16x128] @ Wdg^T ----
    float D1[4][4] = {};
    {
        const uint32_t xab = smem_u32(xa);
        const int mid = l >> 3;
        const uint32_t abase = xab + ((l & 7) + ((mid & 1) << 3)) * 272 + ((mid >> 1) << 4);
        const uint32_t* wdgw = (const uint32_t*)wdg_s;
        #pragma unroll
        for (int kt = 0; kt < 8; kt++) {
            uint32_t a0, a1, a2, a3;
            ldsm4(a0, a1, a2, a3, abase + kt * 32);
            #pragma unroll
            for (int j = 0; j < 4; j++) {
                const uint32_t* bp = wdgw + (8 * j + gr) * 68 + kt * 8 + gc;
                mma16816(D1[j], a0, a1, a2, a3, bp[0], bp[4]);
            }
        }
    }

    // ---- epilogue 1: LN finalize + exact GELU; pack into GEMM2 A-frags ----
    uint32_t A2[2][4];
    #pragma unroll
    for (int j = 0; j < 4; j++) {
        const int k0 = 8 * j + 2 * gc;
        const float2 Pp = *(const float2*)(P_s + k0);
        const float2 Qp = *(const float2*)(Q_s + k0);
        float v00 = rs0 * (D1[j][0] - mu0 * Pp.x) + Qp.x;
        float v01 = rs0 * (D1[j][1] - mu0 * Pp.y) + Qp.y;
        float v10 = rs1 * (D1[j][2] - mu1 * Pp.x) + Qp.x;
        float v11 = rs1 * (D1[j][3] - mu1 * Pp.y) + Qp.y;
        v00 = 0.5f * v00 * (1.f + erff(v00 * 0.7071067811865476f));
        v01 = 0.5f * v01 * (1.f + erff(v01 * 0.7071067811865476f));
        v10 = 0.5f * v10 * (1.f + erff(v10 * 0.7071067811865476f));
        v11 = 0.5f * v11 * (1.f + erff(v11 * 0.7071067811865476f));
        A2[j >> 1][(j & 1) << 1]       = pack_bf16(v01, v00);
        A2[j >> 1][((j & 1) << 1) | 1] = pack_bf16(v11, v10);
    }
    __syncwarp();   // x tile fully consumed before staging overwrites it

    // ---- GEMM2 (two 64-col halves, 2 j-groups each to cap live regs) ----
    const uint32_t* wutw = (const uint32_t*)wut_s;
    __nv_bfloat16* hb = g_h + tok0 * HD + h * 128;
    float* stw = st_s + w * 256;
    #pragma unroll
    for (int half = 0; half < 2; half++) {
        #pragma unroll
        for (int jg = 0; jg < 2; jg++) {
            float D2[4][4] = {};
            #pragma unroll
            for (int jj = 0; jj < 4; jj++) {
                const int j = jg * 4 + jj;
                const uint32_t* bp = wutw + (half * 64 + 8 * j + gr) * 20 + gc;
                mma16816(D2[jj], A2[0][0], A2[0][1], A2[0][2], A2[0][3], bp[0], bp[4]);
                mma16816(D2[jj], A2[1][0], A2[1][1], A2[1][2], A2[1][3], bp[8], bp[12]);
            }
            #pragma unroll
            for (int jj = 0; jj < 4; jj++) {
                const int j = jg * 4 + jj;
                const int n0 = half * 64 + 8 * j + 2 * gc;
                const float2 bb = *(const float2*)(bu_s + n0);
                uint32_t p0 = pack_bf16(D2[jj][1] + bb.y, D2[jj][0] + bb.x);
                uint32_t p1 = pack_bf16(D2[jj][3] + bb.y, D2[jj][2] + bb.x);
                xaw[gr * 68 + half * 32 + 4 * j + gc]       = p0;
                xaw[(gr + 8) * 68 + half * 32 + 4 * j + gc] = p1;
            }
        }
        __syncwarp();
        // coalesced h store + per-lane BN partials (4 features x 8 rows)
        float s0=0,s1=0,s2=0,s3=0,q0=0,q1=0,q2=0,q3=0;
        const int c = l & 15;
        #pragma unroll
        for (int i = 0; i < 8; i++) {
            const int r = i * 2 + (l >> 4);
            uint2 v = *(const uint2*)(xaw + r * 68 + half * 32 + c * 2);
            *(uint2*)(hb + (size_t)r * HD + half * 64 + c * 4) = v;
            float2 f01 = __bfloat1622float2(*(const __nv_bfloat162*)&v.x);
            float2 f23 = __bfloat1622float2(*(const __nv_bfloat162*)&v.y);
            s0 += f01.x; s1 += f01.y; s2 += f23.x; s3 += f23.y;
            q0 += f01.x*f01.x; q1 += f01.y*f01.y; q2 += f23.x*f23.x; q3 += f23.y*f23.y;
        }
        // combine the two row-parities (lane l with l^16 share features)
        s0 += __shfl_xor_sync(0xffffffffu, s0, 16);
        s1 += __shfl_xor_sync(0xffffffffu, s1, 16);
        s2 += __shfl_xor_sync(0xffffffffu, s2, 16);
        s3 += __shfl_xor_sync(0xffffffffu, s3, 16);
        q0 += __shfl_xor_sync(0xffffffffu, q0, 16);
        q1 += __shfl_xor_sync(0xffffffffu, q1, 16);
        q2 += __shfl_xor_sync(0xffffffffu, q2, 16);
        q3 += __shfl_xor_sync(0xffffffffu, q3, 16);
        if (l < 16) {
            *(float4*)(stw + half * 64 + c * 4)       = make_float4(s0, s1, s2, s3);
            *(float4*)(stw + 128 + half * 64 + c * 4) = make_float4(q0, q1, q2, q3);
        }
        __syncwarp();
    }
    __syncthreads();

    // deterministic block reduce over 8 warps -> per-(head,block) partials
    float a2 = 0.f;
    #pragma unroll
    for (int w2 = 0; w2 < 8; w2++) a2 += st_s[w2 * 256 + tid];
    g_part[((size_t)h * 256 + blockIdx.x) * 256 + tid] = a2;
}

// ---------------------------------------------------------------------------
// K2a: stage-1 reduce. grid = (8 slices, H), block = 256. Coalesced rows.
// ---------------------------------------------------------------------------
__global__ void __launch_bounds__(256) adapter_k2a()
{
    const int sl = blockIdx.x, h = blockIdx.y, tid = threadIdx.x;
    const float* gp = g_part + ((size_t)h * 256 + sl * 32) * 256 + tid;
    float acc = 0.f;
    #pragma unroll 8
    for (int r = 0; r < 32; r++) acc += gp[(size_t)r * 256];
    g_mid[(h * 8 + sl) * 256 + tid] = acc;
}

// ---------------------------------------------------------------------------
// K2b: finalize BN affine. grid = H, block = 128.
// ---------------------------------------------------------------------------
__global__ void __launch_bounds__(128) adapter_k2b(const float* __restrict__ bng,
                                                   const float* __restrict__ bnb)
{
    const int h = blockIdx.x, fl = threadIdx.x;
    float S = 0.f, Q = 0.f;
    #pragma unroll
    for (int sl = 0; sl < 8; sl++) {
        S += g_mid[(h * 8 + sl) * 256 + fl];
        Q += g_mid[(h * 8 + sl) * 256 + 128 + fl];
    }
    const int f = h * 128 + fl;
    const float inv = 1.f / (float)NTOK;
    const float mu  = S * inv;
    const float var = fmaxf(Q * inv - mu * mu, 0.f);
    const float rsv = rsqrtf(var + 1e-5f);
    const float g = bng[f], bb = bnb[f];
    g_A[f] = 0.1f * g * rsv;
    g_C[f] = 0.1f * (bb - mu * rsv * g);
}

// ---------------------------------------------------------------------------
// K3: out = h*A + C + x (h is bf16; streaming).
// ---------------------------------------------------------------------------
__global__ void __launch_bounds__(256) adapter_k3(const float* __restrict__ x,
                                                  float* __restrict__ out)
{
    const size_t i = (size_t)blockIdx.x * 256 + threadIdx.x;
    const uint2 hraw = ((const uint2*)g_h)[i];
    const float4 xv = ((const float4*)x)[i];
    float2 f01 = __bfloat1622float2(*(const __nv_bfloat162*)&hraw.x);
    float2 f23 = __bfloat1622float2(*(const __nv_bfloat162*)&hraw.y);
    const int col = (int)((i * 4) & (HD - 1));
    const float4 a = *(const float4*)(g_A + col);
    const float4 c = *(const float4*)(g_C + col);
    float4 r;
    r.x = f01.x * a.x + c.x + xv.x;
    r.y = f01.y * a.y + c.y + xv.y;
    r.z = f23.x * a.z + c.z + xv.z;
    r.w = f23.y * a.w + c.w + xv.w;
    ((float4*)out)[i] = r;
}

// ---------------------------------------------------------------------------
extern "C" void kernel_launch(void* const* d_in, const int* in_sizes, int n_in,
                              void* d_out, int out_size)
{
    const float* x   = (const float*)d_in[0];
    const float* lng = (const float*)d_in[1];
    const float* lnb = (const float*)d_in[2];
    const float* wd  = (const float*)d_in[3];
    const float* bd  = (const float*)d_in[4];
    const float* wu  = (const float*)d_in[5];
    const float* bu  = (const float*)d_in[6];
    const float* bng = (const float*)d_in[7];
    const float* bnb = (const float*)d_in[8];
    float* out = (float*)d_out;

    cudaFuncSetAttribute(adapter_k1, cudaFuncAttributeMaxDynamicSharedMemorySize, SMEM_BYTES);

    adapter_k0<<<32, 128>>>(lng, lnb, wd, bd, wu);
    adapter_k1<<<dim3(256, H_), 256, SMEM_BYTES>>>(x, bu);
    adapter_k2a<<<dim3(8, H_), 256>>>();
    adapter_k2b<<<H_, 128>>>(bng, bnb);
    adapter_k3<<<(NTOK * HD) / (256 * 4), 256>>>(x, out);
}

// round 15
// speedup vs baseline: 1.3109x; 1.0486x over previous
#include <cuda_runtime.h>
#include <cuda_bf16.h>
#include <math.h>
#include <stdint.h>

// Problem constants: B=8, S=4096, H=8, D=128, K=32
#define H_   8
#define D_   128
#define K_   32
#define NTOK 32768
#define HD   1024

typedef unsigned long long u64;

__device__ __forceinline__ uint32_t pack_bf16(float hi, float lo) {
    uint32_t r;
    asm("cvt.rn.bf16x2.f32 %0, %1, %2;" : "=r"(r) : "f"(hi), "f"(lo));
    return r;
}
static __device__ __forceinline__ uint32_t smem_u32(const void* p) {
    uint32_t a;
    asm("{ .reg .u64 t; cvta.to.shared.u64 t, %1; cvt.u32.u64 %0, t; }" : "=r"(a) : "l"(p));
    return a;
}
__device__ __forceinline__ void ldsm4(uint32_t& a0, uint32_t& a1, uint32_t& a2, uint32_t& a3,
                                      uint32_t addr) {
    asm volatile("ldmatrix.sync.aligned.m8n8.x4.shared.b16 {%0,%1,%2,%3}, [%4];"
                 : "=r"(a0), "=r"(a1), "=r"(a2), "=r"(a3) : "r"(addr));
}
__device__ __forceinline__ void mma16816(float* d, uint32_t a0, uint32_t a1, uint32_t a2,
                                         uint32_t a3, uint32_t b0, uint32_t b1) {
    asm volatile("mma.sync.aligned.m16n8k16.row.col.f32.bf16.bf16.f32 "
                 "{%0,%1,%2,%3}, {%4,%5,%6,%7}, {%8,%9}, {%0,%1,%2,%3};"
                 : "+f"(d[0]), "+f"(d[1]), "+f"(d[2]), "+f"(d[3])
                 : "r"(a0), "r"(a1), "r"(a2), "r"(a3), "r"(b0), "r"(b1));
}
// bf16x2 word -> packed f32x2 {lo<<16, hi&mask} — BOTH exact
__device__ __forceinline__ u64 pk_exact(uint32_t w) {
    u64 d;
    asm("{ .reg .b32 lo, hi; shl.b32 lo, %1, 16; and.b32 hi, %1, 0xffff0000;"
        " mov.b64 %0, {lo, hi}; }" : "=l"(d) : "r"(w));
    return d;
}
__device__ __forceinline__ u64 add2(u64 a, u64 b) {
    u64 d;
    asm("add.rn.f32x2 %0, %1, %2;" : "=l"(d) : "l"(a), "l"(b));
    return d;
}
__device__ __forceinline__ u64 ffma2(u64 a, u64 b, u64 c) {
    u64 d;
    asm("fma.rn.f32x2 %0, %1, %2, %3;" : "=l"(d) : "l"(a), "l"(b), "l"(c));
    return d;
}
__device__ __forceinline__ float2 unpack2(u64 v) {
    float2 r;
    asm("mov.b64 {%0, %1}, %2;" : "=f"(r.x), "=f"(r.y) : "l"(v));
    return r;
}

// Scratch
__device__ __nv_bfloat16 g_h[(size_t)NTOK * HD];        // 64 MB h (bf16)
__device__ float g_part[H_ * 64 * 256];                 // per-(head,block) BN partials
__device__ float g_A[HD];
__device__ float g_C[HD];
__device__ __align__(16) __nv_bfloat16 g_wdg[H_ * 32 * 136];  // [h][k][d], stride 136
__device__ __align__(16) __nv_bfloat16 g_wut[H_ * 128 * 40];  // [h][d][k], stride 40
__device__ float g_P[H_ * K_], g_Q[H_ * K_];

// Dynamic SMEM layout for K1 (bytes)
#define SO_WDG 0          // 8704
#define SO_WUT 8704       // 10240
#define SO_BUB 18944      // 512
#define SO_P   19456      // 128
#define SO_Q   19584      // 128
#define SO_XA  19712      // 8 warps * 16*136*2 = 34816
#define SO_ST  54528      // 8 warps * 256 floats = 8192 (BN partials)
#define SMEM_BYTES 62720

// ---------------------------------------------------------------------------
// K0: weight preprocessing. grid = 32 (4 per head), block = 128.
// ---------------------------------------------------------------------------
__global__ void __launch_bounds__(128) adapter_k0(
    const float* __restrict__ lng, const float* __restrict__ lnb,
    const float* __restrict__ wd,  const float* __restrict__ bd,
    const float* __restrict__ wu)
{
    const int h = blockIdx.x >> 2, p = blockIdx.x & 3;
    const int tid = threadIdx.x;
    for (int i = p * 1024 + tid; i < (p + 1) * 1024; i += 128) {
        int d = i >> 5, k = i & 31;                      // wd[h][d][k]
        g_wdg[h * 4352 + k * 136 + d] =
            __float2bfloat16(lng[h * 128 + d] * wd[h * 4096 + i]);
    }
    for (int i = p * 1024 + tid; i < (p + 1) * 1024; i += 128) {
        int k = i >> 7, d = i & 127;                     // wu[h][k][d]
        g_wut[h * 5120 + d * 40 + k] = __float2bfloat16(wu[h * 4096 + i]);
    }
    if (p == 0 && tid < K_) {
        float pp = 0.f, q = bd[h * K_ + tid];
        #pragma unroll 4
        for (int d = 0; d < D_; d++) {
            float v = lng[h * 128 + d] * wd[h * 4096 + d * 32 + tid];
            pp += __bfloat162float(__float2bfloat16(v));  // bf16-rounded, as GEMM sees
            q += lnb[h * 128 + d] * wd[h * 4096 + d * 32 + tid];
        }
        g_P[h * K_ + tid] = pp;
        g_Q[h * K_ + tid] = q;
    }
}

// ---------------------------------------------------------------------------
// K1: persistent HMMA pipeline. grid = (64, H), block = 256 (8 warps).
// Each block processes 4 tiles of 128 tokens; warp = 16 tokens per tile.
//   down[k] = rs*(S[k] - mu*P[k]) + Q[k];  S from mma on raw bf16 x.
// ---------------------------------------------------------------------------
__global__ void __launch_bounds__(256, 3) adapter_k1(
    const float* __restrict__ x, const float* __restrict__ bu)
{
    extern __shared__ __align__(16) char smc[];
    __nv_bfloat16* wdg_s = (__nv_bfloat16*)(smc + SO_WDG);
    __nv_bfloat16* wut_s = (__nv_bfloat16*)(smc + SO_WUT);
    float* bu_s = (float*)(smc + SO_BUB);
    float* P_s  = (float*)(smc + SO_P);
    float* Q_s  = (float*)(smc + SO_Q);
    float* st_s = (float*)(smc + SO_ST);

    const int tid = threadIdx.x;
    const int h = blockIdx.y;

    {   // weights -> SMEM (shared by 8 warps, amortized over 4 tiles)
        const uint4* s1 = (const uint4*)(g_wdg + h * 4352);
        uint4* d1 = (uint4*)wdg_s;
        for (int i = tid; i < 544; i += 256) d1[i] = s1[i];
        const uint4* s2 = (const uint4*)(g_wut + h * 5120);
        uint4* d2 = (uint4*)wut_s;
        for (int i = tid; i < 640; i += 256) d2[i] = s2[i];
        if (tid < 32) { P_s[tid] = g_P[h * K_ + tid]; Q_s[tid] = g_Q[h * K_ + tid]; }
        if (tid < 128) bu_s[tid] = bu[h * 128 + tid];
    }
    __syncthreads();

    const int w = tid >> 5, l = tid & 31;
    const int gr = l >> 2, gc = l & 3;
    __nv_bfloat16* xa = (__nv_bfloat16*)(smc + SO_XA) + w * (16 * 136);
    uint32_t* xaw = (uint32_t*)xa;

    // BN accumulators across tiles: feature = half*64 + (l&15)*4 + e
    float bnS[8] = {0,0,0,0,0,0,0,0};
    float bnQ[8] = {0,0,0,0,0,0,0,0};

    for (int t = 0; t < 4; t++) {
        const size_t tok0 = ((size_t)blockIdx.x * 4 + t) * 128 + (size_t)w * 16;
        const float* xb = x + tok0 * HD + h * 128;

        // ---- load x -> bf16 tile ----
        #pragma unroll
        for (int r = 0; r < 16; r++) {
            float4 v = *(const float4*)(xb + (size_t)r * HD + l * 4);
            *(uint2*)((char*)xa + r * 272 + l * 8) =
                make_uint2(pack_bf16(v.y, v.x), pack_bf16(v.w, v.z));
        }
        __syncwarp();

        // ---- LN stats (exact f32x2 on rounded values) ----
        float mu0, rs0, mu1, rs1;
        {
            const uint4* rp = (const uint4*)((const char*)xa + (l & 15) * 272 + (l >> 4) * 128);
            u64 s2 = 0ull, q2 = 0ull;
            #pragma unroll
            for (int i = 0; i < 8; i++) {
                uint4 v = rp[i];
                u64 p0 = pk_exact(v.x), p1 = pk_exact(v.y);
                u64 p2 = pk_exact(v.z), p3 = pk_exact(v.w);
                s2 = add2(s2, p0); q2 = ffma2(p0, p0, q2);
                s2 = add2(s2, p1); q2 = ffma2(p1, p1, q2);
                s2 = add2(s2, p2); q2 = ffma2(p2, p2, q2);
                s2 = add2(s2, p3); q2 = ffma2(p3, p3, q2);
            }
            float2 sf = unpack2(s2), qf = unpack2(q2);
            float s = sf.x + sf.y, q = qf.x + qf.y;
            s += __shfl_xor_sync(0xffffffffu, s, 16);
            q += __shfl_xor_sync(0xffffffffu, q, 16);
            const float mu = s * (1.f / 128.f);
            const float rs = rsqrtf(fmaxf(q * (1.f / 128.f) - mu * mu, 0.f) + 1e-5f);
            mu0 = __shfl_sync(0xffffffffu, mu, gr);
            rs0 = __shfl_sync(0xffffffffu, rs, gr);
            mu1 = __shfl_sync(0xffffffffu, mu, gr + 8);
            rs1 = __shfl_sync(0xffffffffu, rs, gr + 8);
        }

        // ---- GEMM1 ----
        float D1[4][4] = {};
        {
            const uint32_t xab = smem_u32(xa);
            const int mid = l >> 3;
            const uint32_t abase = xab + ((l & 7) + ((mid & 1) << 3)) * 272 + ((mid >> 1) << 4);
            const uint32_t* wdgw = (const uint32_t*)wdg_s;
            #pragma unroll
            for (int kt = 0; kt < 8; kt++) {
                uint32_t a0, a1, a2, a3;
                ldsm4(a0, a1, a2, a3, abase + kt * 32);
                #pragma unroll
                for (int j = 0; j < 4; j++) {
                    const uint32_t* bp = wdgw + (8 * j + gr) * 68 + kt * 8 + gc;
                    mma16816(D1[j], a0, a1, a2, a3, bp[0], bp[4]);
                }
            }
        }

        // ---- epilogue 1: LN finalize + exact GELU -> A2 frags ----
        uint32_t A2[2][4];
        #pragma unroll
        for (int j = 0; j < 4; j++) {
            const int k0 = 8 * j + 2 * gc;
            const float2 Pp = *(const float2*)(P_s + k0);
            const float2 Qp = *(const float2*)(Q_s + k0);
            float v00 = rs0 * (D1[j][0] - mu0 * Pp.x) + Qp.x;
            float v01 = rs0 * (D1[j][1] - mu0 * Pp.y) + Qp.y;
            float v10 = rs1 * (D1[j][2] - mu1 * Pp.x) + Qp.x;
            float v11 = rs1 * (D1[j][3] - mu1 * Pp.y) + Qp.y;
            v00 = 0.5f * v00 * (1.f + erff(v00 * 0.7071067811865476f));
            v01 = 0.5f * v01 * (1.f + erff(v01 * 0.7071067811865476f));
            v10 = 0.5f * v10 * (1.f + erff(v10 * 0.7071067811865476f));
            v11 = 0.5f * v11 * (1.f + erff(v11 * 0.7071067811865476f));
            A2[j >> 1][(j & 1) << 1]       = pack_bf16(v01, v00);
            A2[j >> 1][((j & 1) << 1) | 1] = pack_bf16(v11, v10);
        }
        __syncwarp();   // x tile fully consumed before staging overwrites it

        // ---- GEMM2 (two 64-col halves, 2 j-groups each) ----
        const uint32_t* wutw = (const uint32_t*)wut_s;
        __nv_bfloat16* hb = g_h + tok0 * HD + h * 128;
        #pragma unroll
        for (int half = 0; half < 2; half++) {
            #pragma unroll
            for (int jg = 0; jg < 2; jg++) {
                float D2[4][4] = {};
                #pragma unroll
                for (int jj = 0; jj < 4; jj++) {
                    const int j = jg * 4 + jj;
                    const uint32_t* bp = wutw + (half * 64 + 8 * j + gr) * 20 + gc;
                    mma16816(D2[jj], A2[0][0], A2[0][1], A2[0][2], A2[0][3], bp[0], bp[4]);
                    mma16816(D2[jj], A2[1][0], A2[1][1], A2[1][2], A2[1][3], bp[8], bp[12]);
                }
                #pragma unroll
                for (int jj = 0; jj < 4; jj++) {
                    const int j = jg * 4 + jj;
                    const int n0 = half * 64 + 8 * j + 2 * gc;
                    const float2 bb = *(const float2*)(bu_s + n0);
                    uint32_t p0 = pack_bf16(D2[jj][1] + bb.y, D2[jj][0] + bb.x);
                    uint32_t p1 = pack_bf16(D2[jj][3] + bb.y, D2[jj][2] + bb.x);
                    xaw[gr * 68 + half * 32 + 4 * j + gc]       = p0;
                    xaw[(gr + 8) * 68 + half * 32 + 4 * j + gc] = p1;
                }
            }
            __syncwarp();
            // coalesced h store + BN register accumulation
            const int c = l & 15;
            #pragma unroll
            for (int i = 0; i < 8; i++) {
                const int r = i * 2 + (l >> 4);
                uint2 v = *(const uint2*)(xaw + r * 68 + half * 32 + c * 2);
                *(uint2*)(hb + (size_t)r * HD + half * 64 + c * 4) = v;
                float2 f01 = __bfloat1622float2(*(const __nv_bfloat162*)&v.x);
                float2 f23 = __bfloat1622float2(*(const __nv_bfloat162*)&v.y);
                bnS[half*4+0] += f01.x; bnS[half*4+1] += f01.y;
                bnS[half*4+2] += f23.x; bnS[half*4+3] += f23.y;
                bnQ[half*4+0] += f01.x*f01.x; bnQ[half*4+1] += f01.y*f01.y;
                bnQ[half*4+2] += f23.x*f23.x; bnQ[half*4+3] += f23.y*f23.y;
            }
            __syncwarp();
        }
    }

    // ---- combine row-parities (l with l^16 share features), stage partials ----
    #pragma unroll
    for (int i = 0; i < 8; i++) {
        bnS[i] += __shfl_xor_sync(0xffffffffu, bnS[i], 16);
        bnQ[i] += __shfl_xor_sync(0xffffffffu, bnQ[i], 16);
    }
    float* stw = st_s + w * 256;
    if (l < 16) {
        const int c = l;
        *(float4*)(stw + c * 4)            = make_float4(bnS[0], bnS[1], bnS[2], bnS[3]);
        *(float4*)(stw + 64 + c * 4)       = make_float4(bnS[4], bnS[5], bnS[6], bnS[7]);
        *(float4*)(stw + 128 + c * 4)      = make_float4(bnQ[0], bnQ[1], bnQ[2], bnQ[3]);
        *(float4*)(stw + 192 + c * 4)      = make_float4(bnQ[4], bnQ[5], bnQ[6], bnQ[7]);
    }
    __syncthreads();

    // deterministic block reduce over 8 warps -> per-(head,block) partials
    float a2 = 0.f;
    #pragma unroll
    for (int w2 = 0; w2 < 8; w2++) a2 += st_s[w2 * 256 + tid];
    g_part[((size_t)h * 64 + blockIdx.x) * 256 + tid] = a2;
}

// ---------------------------------------------------------------------------
// K2: reduce 64 partial rows per head; fold BN into affine. grid = H, block 256.
// ---------------------------------------------------------------------------
__global__ void __launch_bounds__(256) adapter_k2(const float* __restrict__ bng,
                                                  const float* __restrict__ bnb)
{
    __shared__ float buf[256];
    const int h = blockIdx.x, tid = threadIdx.x;
    const float* gp = g_part + (size_t)h * 64 * 256 + tid;
    float acc = 0.f;
    #pragma unroll 8
    for (int b = 0; b < 64; b++) acc += gp[(size_t)b * 256];
    buf[tid] = acc;
    __syncthreads();
    if (tid < 128) {
        const int f = h * 128 + tid;
        const float S = buf[tid], Q = buf[tid + 128];
        const float inv = 1.f / (float)NTOK;
        const float mu  = S * inv;
        const float var = fmaxf(Q * inv - mu * mu, 0.f);
        const float rsv = rsqrtf(var + 1e-5f);
        const float g = bng[f], bb = bnb[f];
        g_A[f] = 0.1f * g * rsv;
        g_C[f] = 0.1f * (bb - mu * rsv * g);
    }
}

// ---------------------------------------------------------------------------
// K3: out = h*A + C + x (h is bf16; streaming).
// ---------------------------------------------------------------------------
__global__ void __launch_bounds__(256) adapter_k3(const float* __restrict__ x,
                                                  float* __restrict__ out)
{
    const size_t i = (size_t)blockIdx.x * 256 + threadIdx.x;
    const uint2 hraw = ((const uint2*)g_h)[i];
    const float4 xv = ((const float4*)x)[i];
    float2 f01 = __bfloat1622float2(*(const __nv_bfloat162*)&hraw.x);
    float2 f23 = __bfloat1622float2(*(const __nv_bfloat162*)&hraw.y);
    const int col = (int)((i * 4) & (HD - 1));
    const float4 a = *(const float4*)(g_A + col);
    const float4 c = *(const float4*)(g_C + col);
    float4 r;
    r.x = f01.x * a.x + c.x + xv.x;
    r.y = f01.y * a.y + c.y + xv.y;
    r.z = f23.x * a.z + c.z + xv.z;
    r.w = f23.y * a.w + c.w + xv.w;
    ((float4*)out)[i] = r;
}

// ---------------------------------------------------------------------------
extern "C" void kernel_launch(void* const* d_in, const int* in_sizes, int n_in,
                              void* d_out, int out_size)
{
    const float* x   = (const float*)d_in[0];
    const float* lng = (const float*)d_in[1];
    const float* lnb = (const float*)d_in[2];
    const float* wd  = (const float*)d_in[3];
    const float* bd  = (const float*)d_in[4];
    const float* wu  = (const float*)d_in[5];
    const float* bu  = (const float*)d_in[6];
    const float* bng = (const float*)d_in[7];
    const float* bnb = (const float*)d_in[8];
    float* out = (float*)d_out;

    cudaFuncSetAttribute(adapter_k1, cudaFuncAttributeMaxDynamicSharedMemorySize, SMEM_BYTES);

    adapter_k0<<<32, 128>>>(lng, lnb, wd, bd, wu);
    adapter_k1<<<dim3(64, H_), 256, SMEM_BYTES>>>(x, bu);
    adapter_k2<<<H_, 256>>>(bng, bnb);
    adapter_k3<<<(NTOK * HD) / (256 * 4), 256>>>(x, out);
}